// round 16
// baseline (speedup 1.0000x reference)
#include <cuda_runtime.h>

// LSTM B=4096, T=999, I=1, H=51, O=1, future=0.
//
// R10 (best: 2731 us) + ONE change: no STG in the hot loop.
//   __syncthreads drains pending stores; warp 3 posted 10 global STG.32
//   right before the barrier EVERY step -> each step's barrier waited on
//   L2 store commit (est. 300-600 cyc/step of the unexplained residual).
//   Fix: FC writes y(t-1) into xsh[t-1][b] -- the x slot consumed one step
//   earlier (zero extra SMEM, no aliasing) -- and the output is flushed
//   coalesced once after the loop. In-loop global stores: gone.
// Everything else identical to R10: BT=10, grid=410 (single wave, 3
// CTAs/SM), gate-pair threads p0=(i,g)/p1=(f,o)+cell, 104 weight regs,
// tanh.approx activations, one barrier/step, batch-major h.

#define HID    51
#define KP     26
#define SEQLEN 999
#define BT     10
#define NTHR   128
#define BATCH  4096
#define GRID   410          // ceil(4096/10)

typedef unsigned long long u64;
template <int N> struct IC { static constexpr int v = N; };

__device__ __forceinline__ u64 pk2(float lo, float hi) {
    u64 r;
    asm("mov.b64 %0, {%1, %2};"
        : "=l"(r) : "r"(__float_as_uint(lo)), "r"(__float_as_uint(hi)));
    return r;
}
__device__ __forceinline__ void upk2(u64 v, float& lo, float& hi) {
    unsigned a, b;
    asm("mov.b64 {%0, %1}, %2;" : "=r"(a), "=r"(b) : "l"(v));
    lo = __uint_as_float(a); hi = __uint_as_float(b);
}
__device__ __forceinline__ u64 ffma2(u64 a, u64 b, u64 c) {
    u64 d; asm("fma.rn.f32x2 %0, %1, %2, %3;" : "=l"(d) : "l"(a), "l"(b), "l"(c));
    return d;
}
__device__ __forceinline__ u64 fmul2(u64 a, u64 b) {
    u64 d; asm("mul.rn.f32x2 %0, %1, %2;" : "=l"(d) : "l"(a), "l"(b));
    return d;
}
__device__ __forceinline__ float tanha(float x) {
    float r; asm("tanh.approx.f32 %0, %1;" : "=f"(r) : "f"(x));
    return r;
}

__global__ __launch_bounds__(NTHR, 3)
void lstm14_kernel(const float* __restrict__ input,   // (B, T, 1)
                   const float* __restrict__ W_ih,    // (4H, 1)
                   const float* __restrict__ W_hh,    // (4H, H)
                   const float* __restrict__ b_ih,    // (4H)
                   const float* __restrict__ b_hh,    // (4H)
                   const float* __restrict__ W_fc,    // (1, H)
                   const float* __restrict__ b_fc,    // (1)
                   float* __restrict__ out)           // (B, T, 1)
{
    // xsh doubles as the y buffer: slot [t] holds x until step t consumes
    // it, then step t+1's FC overwrites it with y(t). Flushed at the end.
    __shared__ __align__(16) float xsh[SEQLEN][BT];   // 39.96 KB
    __shared__ __align__(16) u64   hsh[2][BT][KP];    // 4.16 KB, batch-major
    __shared__ __align__(16) u64   wfc2[KP];

    const int tid = threadIdx.x;
    const int b0  = blockIdx.x * BT;

    // ---- one-time init (batch-clamped for the last CTA) ----
    #pragma unroll
    for (int b = 0; b < BT; b++) {
        const int bidx = min(b0 + b, BATCH - 1);
        for (int idx = tid; idx < SEQLEN; idx += NTHR)
            xsh[idx][b] = input[bidx * SEQLEN + idx];
    }
    for (int idx = tid; idx < 2 * BT * KP; idx += NTHR)
        ((u64*)hsh)[idx] = 0ull;                      // h0 = 0 (+ pad lanes)
    if (tid < KP)
        wfc2[tid] = pk2(W_fc[2 * tid],
                        (2 * tid + 1 < HID) ? W_fc[2 * tid + 1] : 0.0f);

    const int j = tid >> 1;           // unit 0..50 (active)
    const int p = tid & 1;            // 0 = (i,g), 1 = (f,o)+cell
    const bool active = (tid < 2 * HID);              // < 102
    const bool fcRole = (tid >= 104 && tid < 104 + BT);
    const int  fb     = tid - 104;
    const unsigned wmask = (tid >= 96) ? 0x3Fu : 0xFFFFFFFFu;

    const int row1 = p * HID + j;         // i or f
    const int row2 = (2 + p) * HID + j;   // g or o

    u64 w1[KP], w2[KP];
    float bias1 = 0.f, bias2 = 0.f, wih1 = 0.f, wih2 = 0.f;
    if (active) {
        #pragma unroll
        for (int q = 0; q < KP; q++) {
            int k0 = 2 * q, k1 = 2 * q + 1;
            float a0 = W_hh[row1 * HID + k0];
            float a1 = (k1 < HID) ? W_hh[row1 * HID + k1] : 0.0f;
            float c0 = W_hh[row2 * HID + k0];
            float c1 = (k1 < HID) ? W_hh[row2 * HID + k1] : 0.0f;
            w1[q] = pk2(a0, a1);
            w2[q] = pk2(c0, c1);
        }
        bias1 = b_ih[row1] + b_hh[row1];
        bias2 = b_ih[row2] + b_hh[row2];
        wih1  = W_ih[row1];
        wih2  = W_ih[row2];
    } else {
        #pragma unroll
        for (int q = 0; q < KP; q++) { w1[q] = 0ull; w2[q] = 0ull; }
    }
    const float bfc = b_fc[0];

    // act = m2 * tanh(sc2 * a) + a2c  (row1 always sigmoid; row2: g->tanh,
    // o->sigmoid).  sigmoid(x) = 0.5*tanh(0.5x) + 0.5.
    const float sc2 = (p == 0) ? 1.0f : 0.5f;
    const float m2  = (p == 0) ? 1.0f : 0.5f;
    const float a2c = (p == 0) ? 0.0f : 0.5f;

    u64 cst0 = 0ull, cst1 = 0ull, cst2 = 0ull, cst3 = 0ull, cst4 = 0ull;

    __syncthreads();

    #pragma unroll 1
    for (int t = 0; t < SEQLEN; t++) {
        const u64* __restrict__ hb = &hsh[t & 1][0][0];
        u64* __restrict__ hw = &hsh[(t + 1) & 1][0][0];
        const float* __restrict__ xrow = &xsh[t][0];

        // ---- deferred FC for step t-1: y -> SMEM (no STG in the loop) ----
        if (fcRole && t > 0) {
            const u64* __restrict__ hv = hb + fb * KP;
            u64 s0 = 0ull, s1 = 0ull;
            #pragma unroll
            for (int q = 0; q < KP; q += 2) {
                s0 = ffma2(hv[q],     wfc2[q],     s0);
                s1 = ffma2(hv[q + 1], wfc2[q + 1], s1);
            }
            float aa, ab, ac, ad;
            upk2(s0, aa, ab); upk2(s1, ac, ad);
            xsh[t - 1][fb] = (aa + ab) + (ac + ad) + bfc;  // x[t-1] consumed
        }

        if (active) {
            // CH-templated chunk: compile-time indices only.
            auto chunkf = [&](auto CHC, int cb, u64& cA, u64& cB) {
                constexpr int CH = CHC.v;
                u64 A[CH], C[CH];
                #pragma unroll
                for (int i = 0; i < CH; i++) { A[i] = 0ull; C[i] = 0ull; }
                #pragma unroll
                for (int q = 0; q < KP; q += 2) {
                    #pragma unroll
                    for (int i = 0; i < CH; i++) {
                        ulonglong2 u = *(const ulonglong2*)(hb + (cb + i) * KP + q);
                        A[i] = ffma2(w1[q], u.x, A[i]);
                        A[i] = ffma2(w1[q + 1], u.y, A[i]);
                        C[i] = ffma2(w2[q], u.x, C[i]);
                        C[i] = ffma2(w2[q + 1], u.y, C[i]);
                    }
                }
                float s1a[CH], s2a[CH];
                #pragma unroll
                for (int i = 0; i < CH; i += 2) {
                    const float2 xv = make_float2(xrow[cb + i], xrow[cb + i + 1]);
                    float lo, hi;
                    upk2(A[i], lo, hi);
                    float g1 = (lo + hi) + fmaf(xv.x, wih1, bias1);
                    upk2(C[i], lo, hi);
                    float g2 = (lo + hi) + fmaf(xv.x, wih2, bias2);
                    s1a[i] = fmaf(0.5f, tanha(0.5f * g1), 0.5f);
                    s2a[i] = fmaf(m2, tanha(sc2 * g2), a2c);
                    upk2(A[i + 1], lo, hi);
                    g1 = (lo + hi) + fmaf(xv.y, wih1, bias1);
                    upk2(C[i + 1], lo, hi);
                    g2 = (lo + hi) + fmaf(xv.y, wih2, bias2);
                    s1a[i + 1] = fmaf(0.5f, tanha(0.5f * g1), 0.5f);
                    s2a[i + 1] = fmaf(m2, tanha(sc2 * g2), a2c);
                }
                #pragma unroll
                for (int pp = 0; pp < CH / 2; pp++) {
                    u64 a1p = pk2(s1a[2 * pp], s1a[2 * pp + 1]);
                    u64 a2p = pk2(s2a[2 * pp], s2a[2 * pp + 1]);
                    u64 pr = fmul2(a1p, a2p);          // p0: sig(i)*tanh(g)
                    u64 rr = __shfl_xor_sync(wmask, pr, 1, 32);
                    if (p == 1) {
                        u64& cc = (pp == 0) ? cA : cB;
                        cc = ffma2(a1p, cc, rr);
                        float c0f, c1f; upk2(cc, c0f, c1f);
                        const float h0v = s2a[2 * pp]     * tanha(c0f);
                        const float h1v = s2a[2 * pp + 1] * tanha(c1f);
                        const int jh = j >> 1, jl = j & 1;
                        ((float*)(hw + (cb + 2 * pp) * KP + jh))[jl]     = h0v;
                        ((float*)(hw + (cb + 2 * pp + 1) * KP + jh))[jl] = h1v;
                    }
                }
            };

            chunkf(IC<4>{}, 0, cst0, cst1);
            asm volatile("" ::: "memory");
            chunkf(IC<4>{}, 4, cst2, cst3);
            asm volatile("" ::: "memory");
            chunkf(IC<2>{}, 8, cst4, cst4);
        }
        __syncthreads();
    }

    // final FC for t = SEQLEN-1 (into SMEM slot SEQLEN-1)
    if (fcRole) {
        const u64* __restrict__ hv = &hsh[SEQLEN & 1][fb][0];
        u64 s0 = 0ull, s1 = 0ull;
        #pragma unroll
        for (int q = 0; q < KP; q += 2) {
            s0 = ffma2(hv[q],     wfc2[q],     s0);
            s1 = ffma2(hv[q + 1], wfc2[q + 1], s1);
        }
        float aa, ab, ac, ad;
        upk2(s0, aa, ab); upk2(s1, ac, ad);
        xsh[SEQLEN - 1][fb] = (aa + ab) + (ac + ad) + bfc;
    }
    __syncthreads();

    // ---- one-time coalesced flush of all outputs ----
    #pragma unroll
    for (int b = 0; b < BT; b++) {
        if (b0 + b < BATCH) {
            for (int idx = tid; idx < SEQLEN; idx += NTHR)
                out[(b0 + b) * SEQLEN + idx] = xsh[idx][b];
        }
    }
}

extern "C" void kernel_launch(void* const* d_in, const int* in_sizes, int n_in,
                              void* d_out, int out_size) {
    const float* input = (const float*)d_in[0];
    const float* W_ih  = (const float*)d_in[1];
    const float* W_hh  = (const float*)d_in[2];
    const float* b_ih  = (const float*)d_in[3];
    const float* b_hh  = (const float*)d_in[4];
    const float* W_fc  = (const float*)d_in[5];
    const float* b_fc  = (const float*)d_in[6];
    // d_in[7] = future (0) — ignored.
    float* out = (float*)d_out;

    lstm14_kernel<<<GRID, NTHR>>>(input, W_ih, W_hh, b_ih, b_hh,
                                  W_fc, b_fc, out);
}